// round 1
// baseline (speedup 1.0000x reference)
#include <cuda_runtime.h>
#include <cuda_bf16.h>
#include <math.h>

// ---------------- problem constants ----------------
#define BB 2
#define LL 2048
#define HH 1536
#define II 3072
#define NN 16
#define RR 96
#define MTOT (BB * LL)   // 4096
#define E2 (2 * II)      // 6144
#define PP (RR + 2 * NN) // 128

// ---------------- scratch (device globals; no allocations allowed) ----------------
__device__ float g_proj[MTOT * (size_t)E2];   // in_proj output [4096, 6144]
__device__ float g_x[MTOT * (size_t)II];      // conv+silu output [4096, 3072]
__device__ float g_ssmp[MTOT * (size_t)PP];   // x_proj output [4096, 128]
__device__ float g_delta[MTOT * (size_t)II];  // softplus(dt+bias) [4096, 3072]
__device__ float g_y[MTOT * (size_t)II];      // scan output (gated) [4096, 3072]

// ---------------- fast math helpers ----------------
__device__ __forceinline__ float fast_ex2(float x) {
    float r;
    asm("ex2.approx.f32 %0, %1;" : "=f"(r) : "f"(x));
    return r;
}

// ---------------- cp.async helpers ----------------
__device__ __forceinline__ void cp16(void* dst_smem, const void* src_gmem) {
    unsigned d = (unsigned)__cvta_generic_to_shared(dst_smem);
    asm volatile("cp.async.cg.shared.global [%0], [%1], 16;" :: "r"(d), "l"(src_gmem));
}
__device__ __forceinline__ void cp_commit() {
    asm volatile("cp.async.commit_group;");
}
__device__ __forceinline__ void cp_wait1() {
    asm volatile("cp.async.wait_group 1;" ::: "memory");
}
__device__ __forceinline__ void cp_wait0() {
    asm volatile("cp.async.wait_group 0;" ::: "memory");
}

// ============================================================================
// SGEMM NT: C[M,N] = A[M,K] * B[N,K]^T  (row-major, K contiguous in both)
// 128x128 block tile, BK=8, 256 threads, 8x8 per-thread micro tile.
// Requires M%128==0, N%128==0, K%8==0.
// EPI==1: v = softplus(v + bias[col])
// ============================================================================
template <int EPI>
__global__ __launch_bounds__(256)
void sgemm_nt(const float* __restrict__ A, int lda,
              const float* __restrict__ B, int ldb,
              float* __restrict__ C, int ldc,
              int K, const float* __restrict__ bias) {
    __shared__ float As[8][128];
    __shared__ float Bs[8][128];

    const int tid = threadIdx.x;
    const int tx = tid & 15;   // N direction (16)
    const int ty = tid >> 4;   // M direction (16)

    const int lrow = tid >> 1;          // 0..127
    const int lcol = (tid & 1) << 2;    // 0 or 4

    const float* Ap = A + ((size_t)(blockIdx.y * 128 + lrow)) * lda + lcol;
    const float* Bp = B + ((size_t)(blockIdx.x * 128 + lrow)) * ldb + lcol;

    float acc[8][8];
#pragma unroll
    for (int i = 0; i < 8; i++)
#pragma unroll
        for (int j = 0; j < 8; j++) acc[i][j] = 0.0f;

    for (int k0 = 0; k0 < K; k0 += 8) {
        float4 av = *(const float4*)(Ap + k0);
        float4 bv = *(const float4*)(Bp + k0);
        __syncthreads();  // previous iteration's compute must be done
        As[lcol + 0][lrow] = av.x;
        As[lcol + 1][lrow] = av.y;
        As[lcol + 2][lrow] = av.z;
        As[lcol + 3][lrow] = av.w;
        Bs[lcol + 0][lrow] = bv.x;
        Bs[lcol + 1][lrow] = bv.y;
        Bs[lcol + 2][lrow] = bv.z;
        Bs[lcol + 3][lrow] = bv.w;
        __syncthreads();
#pragma unroll
        for (int kk = 0; kk < 8; kk++) {
            float ar[8], br[8];
            *(float4*)&ar[0] = *(const float4*)&As[kk][ty * 8];
            *(float4*)&ar[4] = *(const float4*)&As[kk][ty * 8 + 4];
            *(float4*)&br[0] = *(const float4*)&Bs[kk][tx * 8];
            *(float4*)&br[4] = *(const float4*)&Bs[kk][tx * 8 + 4];
#pragma unroll
            for (int i = 0; i < 8; i++)
#pragma unroll
                for (int j = 0; j < 8; j++) acc[i][j] = fmaf(ar[i], br[j], acc[i][j]);
        }
    }

    const int crow0 = blockIdx.y * 128 + ty * 8;
    const int ccol0 = blockIdx.x * 128 + tx * 8;
#pragma unroll
    for (int i = 0; i < 8; i++) {
        float out4[8];
#pragma unroll
        for (int j = 0; j < 8; j++) {
            float v = acc[i][j];
            if (EPI == 1) {
                v += bias[ccol0 + j];
                v = (v > 20.0f) ? v : log1pf(__expf(v));
            }
            out4[j] = v;
        }
        float* cp = C + (size_t)(crow0 + i) * ldc + ccol0;
        *(float4*)(cp + 0) = *(float4*)&out4[0];
        *(float4*)(cp + 4) = *(float4*)&out4[4];
    }
}

// ============================================================================
// Causal depthwise conv1d (K=4) + SiLU. Reads x half of g_proj, writes g_x.
// ============================================================================
__global__ void conv_silu_kernel(const float* __restrict__ conv_w,
                                 const float* __restrict__ conv_b) {
    int idx = blockIdx.x * blockDim.x + threadIdx.x;
    if (idx >= MTOT * II) return;
    const int i = idx % II;
    const int m = idx / II;
    const int l = m & (LL - 1);

    float acc = conv_b[i];
#pragma unroll
    for (int j = 0; j < 4; j++) {
        int ls = l - 3 + j;
        if (ls >= 0) acc = fmaf(g_proj[(size_t)(m - 3 + j) * E2 + i], conv_w[i * 4 + j], acc);
    }
    // SiLU
    g_x[idx] = acc / (1.0f + __expf(-acc));
}

// ============================================================================
// Selective scan, fused with D-skip and gate*silu(gate).
// Grid: 192 blocks x 128 threads. Block handles 32 channels of one batch.
// Thread = (channel, quarter): 4 state lanes each; y reduced via shfl.
// Inputs staged through shared memory in 32-step chunks via cp.async
// (double-buffered) so the sequential loop is never DRAM-latency bound.
// ============================================================================
#define SCH 32                   // steps per chunk
#define NCHUNK (LL / SCH)        // 64

__global__ __launch_bounds__(128)
void scan_kernel(const float* __restrict__ Amat,   // [I,16]
                 const float* __restrict__ Dvec) { // [I]
    __shared__ __align__(16) float sD[2][SCH * 32];
    __shared__ __align__(16) float sX[2][SCH * 32];
    __shared__ __align__(16) float sBC[2][SCH * 32];
    __shared__ __align__(16) float sY[SCH * 32];

    const int tid = threadIdx.x;
    const int blk = blockIdx.x;          // 0..191
    const int b = blk / 96;              // batch
    const int ibase = (blk % 96) * 32;   // first channel of this block
    const int q = tid & 3;               // state quarter (n = 4q..4q+3)
    const int c = tid >> 2;              // local channel 0..31
    const int i = ibase + c;
    const int mbase = b * LL;

    // per-thread constants
    float a2[4];
#pragma unroll
    for (int n = 0; n < 4; n++)
        a2[n] = Amat[i * NN + q * 4 + n] * 1.4426950408889634f;  // A * log2(e)
    const float dv = Dvec[i];
    float st[4] = {0.0f, 0.0f, 0.0f, 0.0f};

    // stage one chunk: 32 steps x 32 channels of delta, x, and B|C (32 floats)
    auto issue = [&](int buf, int ch) {
        const int m0 = mbase + ch * SCH;
#pragma unroll
        for (int k2 = 0; k2 < 2; k2++) {
            int f = tid + k2 * 128;       // 0..255 (float4 index)
            int l = f >> 3;
            int c4 = (f & 7) * 4;
            int m = m0 + l;
            cp16(&sD[buf][l * 32 + c4], &g_delta[(size_t)m * II + ibase + c4]);
            cp16(&sX[buf][l * 32 + c4], &g_x[(size_t)m * II + ibase + c4]);
            cp16(&sBC[buf][l * 32 + c4], &g_ssmp[(size_t)m * PP + RR + c4]);
        }
    };

    issue(0, 0);
    cp_commit();

    for (int ch = 0; ch < NCHUNK; ch++) {
        const int cur = ch & 1;
        if (ch + 1 < NCHUNK) {
            issue(1 - cur, ch + 1);
            cp_commit();
            cp_wait1();   // chunk ch's group complete, ch+1 in flight
        } else {
            cp_wait0();
        }
        __syncthreads();

        const int m0 = mbase + ch * SCH;
#pragma unroll 4
        for (int l = 0; l < SCH; l++) {
            const float delta = sD[cur][l * 32 + c];
            const float xv = sX[cur][l * 32 + c];
            const float du = delta * xv;
            const float4 Bv = *(const float4*)&sBC[cur][l * 32 + q * 4];
            const float4 Cv = *(const float4*)&sBC[cur][l * 32 + 16 + q * 4];
            float y = 0.0f;
            {
                float dA0 = fast_ex2(delta * a2[0]);
                float dA1 = fast_ex2(delta * a2[1]);
                float dA2 = fast_ex2(delta * a2[2]);
                float dA3 = fast_ex2(delta * a2[3]);
                st[0] = fmaf(st[0], dA0, du * Bv.x);
                st[1] = fmaf(st[1], dA1, du * Bv.y);
                st[2] = fmaf(st[2], dA2, du * Bv.z);
                st[3] = fmaf(st[3], dA3, du * Bv.w);
                y = st[0] * Cv.x + st[1] * Cv.y + st[2] * Cv.z + st[3] * Cv.w;
            }
            y += __shfl_xor_sync(0xffffffffu, y, 1);
            y += __shfl_xor_sync(0xffffffffu, y, 2);
            if (q == 0) {
                const int m = m0 + l;
                const float g = g_proj[(size_t)m * E2 + II + i];  // gate
                const float sg = g / (1.0f + __expf(-g));          // silu(gate)
                sY[l * 32 + c] = (y + xv * dv) * sg;
            }
        }
        __syncthreads();

        // cooperative store of this chunk's y
#pragma unroll
        for (int k2 = 0; k2 < 2; k2++) {
            int f = tid + k2 * 128;
            int l = f >> 3;
            int c4 = (f & 7) * 4;
            int m = m0 + l;
            *(float4*)&g_y[(size_t)m * II + ibase + c4] = *(const float4*)&sY[l * 32 + c4];
        }
        // next iteration's top __syncthreads orders these reads vs. sY rewrite
    }
}

// ============================================================================
// kernel_launch
// ============================================================================
extern "C" void kernel_launch(void* const* d_in, const int* in_sizes, int n_in,
                              void* d_out, int out_size) {
    const float* hs      = (const float*)d_in[0];  // [2,2048,1536]
    const float* W_in    = (const float*)d_in[1];  // [6144,1536]
    const float* conv_w  = (const float*)d_in[2];  // [3072,4]
    const float* conv_b  = (const float*)d_in[3];  // [3072]
    const float* W_x     = (const float*)d_in[4];  // [128,3072]
    const float* W_dt    = (const float*)d_in[5];  // [3072,96]
    const float* dt_bias = (const float*)d_in[6];  // [3072]
    const float* Amat    = (const float*)d_in[7];  // [3072,16]
    const float* Dvec    = (const float*)d_in[8];  // [3072]
    const float* W_out   = (const float*)d_in[9];  // [1536,3072]
    float* out = (float*)d_out;

    float *proj, *x, *ssmp, *delta, *y;
    cudaGetSymbolAddress((void**)&proj, g_proj);
    cudaGetSymbolAddress((void**)&x, g_x);
    cudaGetSymbolAddress((void**)&ssmp, g_ssmp);
    cudaGetSymbolAddress((void**)&delta, g_delta);
    cudaGetSymbolAddress((void**)&y, g_y);

    // 1) in_proj: proj[4096,6144] = hs[4096,1536] @ W_in[6144,1536]^T
    {
        dim3 grid(E2 / 128, MTOT / 128);
        sgemm_nt<0><<<grid, 256>>>(hs, HH, W_in, HH, proj, E2, HH, nullptr);
    }
    // 2) causal conv1d + SiLU -> g_x
    {
        int total = MTOT * II;
        conv_silu_kernel<<<(total + 255) / 256, 256>>>(conv_w, conv_b);
    }
    // 3) x_proj: ssmp[4096,128] = x[4096,3072] @ W_x[128,3072]^T
    {
        dim3 grid(PP / 128, MTOT / 128);
        sgemm_nt<0><<<grid, 256>>>(x, II, W_x, II, ssmp, PP, II, nullptr);
    }
    // 4) dt_proj + softplus: delta[4096,3072] = softplus(ssmp[:, :96] @ W_dt^T + bias)
    {
        dim3 grid(II / 128, MTOT / 128);
        sgemm_nt<1><<<grid, 256>>>(ssmp, PP, W_dt, RR, delta, II, RR, dt_bias);
    }
    // 5) selective scan + D-skip + gate*silu(gate) -> g_y
    scan_kernel<<<192, 128>>>(Amat, Dvec);
    // 6) out_proj: out[4096,1536] = y[4096,3072] @ W_out[1536,3072]^T
    {
        dim3 grid(HH / 128, MTOT / 128);
        sgemm_nt<0><<<grid, 256>>>(y, II, W_out, II, out, HH, II, nullptr);
    }
}

// round 3
// speedup vs baseline: 2.1529x; 2.1529x over previous
#include <cuda_runtime.h>
#include <cuda_bf16.h>
#include <math.h>
#include <stdint.h>

// ---------------- problem constants ----------------
#define BB 2
#define LL 2048
#define HH 1536
#define II 3072
#define NN 16
#define RR 96
#define MTOT 4096
#define E2 6144
#define PP 128

// ---------------- fp32 scratch ----------------
__device__ __align__(256) float g_proj[(size_t)MTOT * E2];   // in_proj output [4096,6144]
__device__ __align__(256) float g_x[(size_t)MTOT * II];      // conv+silu output (fp32 scan input)
__device__ __align__(256) float g_ssmp[(size_t)MTOT * PP];   // x_proj output [4096,128]
__device__ __align__(256) float g_delta[(size_t)MTOT * II];  // softplus(dt+bias)

// ---------------- bf16 split scratch (hi/lo pairs) ----------------
__device__ __align__(256) __nv_bfloat16 g_hs_hi[(size_t)MTOT * HH], g_hs_lo[(size_t)MTOT * HH];
__device__ __align__(256) __nv_bfloat16 g_Win_hi[(size_t)E2 * HH],  g_Win_lo[(size_t)E2 * HH];
__device__ __align__(256) __nv_bfloat16 g_x_hi[(size_t)MTOT * II],  g_x_lo[(size_t)MTOT * II];
__device__ __align__(256) __nv_bfloat16 g_Wx_hi[(size_t)PP * II],   g_Wx_lo[(size_t)PP * II];
__device__ __align__(256) __nv_bfloat16 g_sp_hi[(size_t)MTOT * PP], g_sp_lo[(size_t)MTOT * PP];
__device__ __align__(256) __nv_bfloat16 g_Wdt_hi[(size_t)II * PP],  g_Wdt_lo[(size_t)II * PP]; // K pad 96->128
__device__ __align__(256) __nv_bfloat16 g_y_hi[(size_t)MTOT * II],  g_y_lo[(size_t)MTOT * II];
__device__ __align__(256) __nv_bfloat16 g_Wout_hi[(size_t)HH * II], g_Wout_lo[(size_t)HH * II];

// ---------------- helpers ----------------
__device__ __forceinline__ float fast_ex2(float x) {
    float r; asm("ex2.approx.f32 %0, %1;" : "=f"(r) : "f"(x)); return r;
}
__device__ __forceinline__ uint32_t smem_u32(const void* p) {
    return (uint32_t)__cvta_generic_to_shared(p);
}
__device__ __forceinline__ void cp16(void* dst_smem, const void* src_gmem) {
    unsigned d = smem_u32(dst_smem);
    asm volatile("cp.async.cg.shared.global [%0], [%1], 16;" :: "r"(d), "l"(src_gmem));
}
__device__ __forceinline__ void cp_commit() { asm volatile("cp.async.commit_group;"); }
__device__ __forceinline__ void cp_wait1() { asm volatile("cp.async.wait_group 1;" ::: "memory"); }
__device__ __forceinline__ void cp_wait0() { asm volatile("cp.async.wait_group 0;" ::: "memory"); }

__device__ __forceinline__ void ldsm4(uint32_t& r0, uint32_t& r1, uint32_t& r2, uint32_t& r3,
                                      uint32_t addr) {
    asm volatile("ldmatrix.sync.aligned.m8n8.x4.shared.b16 {%0,%1,%2,%3}, [%4];"
                 : "=r"(r0), "=r"(r1), "=r"(r2), "=r"(r3) : "r"(addr));
}
__device__ __forceinline__ void mma16816(float* d, const uint32_t* a, const uint32_t* b) {
    asm volatile("mma.sync.aligned.m16n8k16.row.col.f32.bf16.bf16.f32 "
                 "{%0,%1,%2,%3}, {%4,%5,%6,%7}, {%8,%9}, {%0,%1,%2,%3};"
                 : "+f"(d[0]), "+f"(d[1]), "+f"(d[2]), "+f"(d[3])
                 : "r"(a[0]), "r"(a[1]), "r"(a[2]), "r"(a[3]), "r"(b[0]), "r"(b[1]));
}

// ============================================================================
// bf16 split GEMM via mma.sync: C[M,N] = A[M,K] * B[N,K]^T (both K-contiguous)
// A ~ Ahi+Alo, B ~ Bhi+Blo; C = Ahi*Bhi + Ahi*Blo + Alo*Bhi (fp32 accum).
// 128x128 CTA tile, BK=64, 3-stage cp.async pipeline, 8 warps (2m x 4n),
// warp tile 64x32 (4x4 m16n8 frags). Requires K % 64 == 0.
// EPI==1: C = softplus(C + bias[col])
// ============================================================================
#define BK 64
#define TILE_B (128 * BK * 2)            // 16384 bytes per matrix tile
#define STAGE_B (4 * TILE_B)             // 65536 per stage
#define GEMM_SMEM (3 * STAGE_B)          // 196608

template <int EPI>
__global__ __launch_bounds__(256)
void gemm_mma(const __nv_bfloat16* __restrict__ Ahi, const __nv_bfloat16* __restrict__ Alo,
              const __nv_bfloat16* __restrict__ Bhi, const __nv_bfloat16* __restrict__ Blo,
              int K, float* __restrict__ C, int ldc, const float* __restrict__ bias) {
    extern __shared__ char smem[];
    const int tid = threadIdx.x;
    const int lane = tid & 31;
    const int wid = tid >> 5;
    const int m0 = blockIdx.y * 128;
    const int n0 = blockIdx.x * 128;
    const int wm = (wid & 1) * 64;       // warp m offset
    const int wn = (wid >> 1) * 32;      // warp n offset
    const int nc = K >> 6;

    float acc[4][4][4] = {};

    auto issue = [&](int c) {
        char* st = smem + (c % 3) * STAGE_B;
        const int k0 = c << 6;
#pragma unroll
        for (int rep = 0; rep < 4; rep++) {
            int idx = tid + rep * 256;      // 0..1023
            int r = idx >> 3;               // row 0..127
            int cc = idx & 7;               // 16B chunk in 128B row
            uint32_t so = (uint32_t)(r * 128 + ((cc ^ (r & 7)) * 16));
            size_t ao = (size_t)(m0 + r) * K + k0 + cc * 8;
            size_t bo = (size_t)(n0 + r) * K + k0 + cc * 8;
            cp16(st + so, Ahi + ao);
            cp16(st + TILE_B + so, Alo + ao);
            cp16(st + 2 * TILE_B + so, Bhi + bo);
            cp16(st + 3 * TILE_B + so, Blo + bo);
        }
    };

    issue(0); cp_commit();
    issue(1); cp_commit();

    // ldmatrix lane geometry (constant across chunks)
    const int a_row = lane & 15;          // row within m16 tile
    const int a_kh = lane >> 4;           // k-half (0/1)
    const int b_nr = (lane & 7) + ((lane >> 4) << 3);  // n row within 16
    const int b_kh = (lane >> 3) & 1;

    for (int c = 0; c < nc; c++) {
        cp_wait1();
        __syncthreads();
        const uint32_t sA = smem_u32(smem + (c % 3) * STAGE_B);
        const uint32_t sB = sA + 2 * TILE_B;

#pragma unroll
        for (int kc = 0; kc < 8; kc += 2) {  // kc = 16B-chunk base (16 bf16 per kstep)
            uint32_t ah[4][4], al[4][4], bh[4][2], bl[4][2];
#pragma unroll
            for (int i = 0; i < 4; i++) {
                int r = wm + i * 16 + a_row;
                uint32_t off = (uint32_t)(r * 128 + (((kc + a_kh) ^ (r & 7)) * 16));
                ldsm4(ah[i][0], ah[i][1], ah[i][2], ah[i][3], sA + off);
                ldsm4(al[i][0], al[i][1], al[i][2], al[i][3], sA + TILE_B + off);
            }
#pragma unroll
            for (int jj = 0; jj < 2; jj++) {
                int r = wn + b_nr + jj * 16;
                uint32_t off = (uint32_t)(r * 128 + (((kc + b_kh) ^ (r & 7)) * 16));
                uint32_t t0, t1, t2, t3;
                ldsm4(t0, t1, t2, t3, sB + off);
                bh[jj * 2][0] = t0; bh[jj * 2][1] = t1;
                bh[jj * 2 + 1][0] = t2; bh[jj * 2 + 1][1] = t3;
                ldsm4(t0, t1, t2, t3, sB + TILE_B + off);
                bl[jj * 2][0] = t0; bl[jj * 2][1] = t1;
                bl[jj * 2 + 1][0] = t2; bl[jj * 2 + 1][1] = t3;
            }
#pragma unroll
            for (int i = 0; i < 4; i++)
#pragma unroll
                for (int j = 0; j < 4; j++) {
                    mma16816(acc[i][j], ah[i], bh[j]);
                    mma16816(acc[i][j], ah[i], bl[j]);
                    mma16816(acc[i][j], al[i], bh[j]);
                }
        }
        __syncthreads();
        if (c + 2 < nc) issue(c + 2);
        cp_commit();
    }

    // epilogue: direct register -> gmem
    const int quad = lane >> 2;
    const int tq = lane & 3;
#pragma unroll
    for (int i = 0; i < 4; i++) {
#pragma unroll
        for (int j = 0; j < 4; j++) {
            int r0 = m0 + wm + i * 16 + quad;
            int cc = n0 + wn + j * 8 + tq * 2;
            float v0 = acc[i][j][0], v1 = acc[i][j][1];
            float v2 = acc[i][j][2], v3 = acc[i][j][3];
            if (EPI == 1) {
                float b0 = bias[cc], b1 = bias[cc + 1];
                v0 += b0; v1 += b1; v2 += b0; v3 += b1;
                v0 = (v0 > 20.0f) ? v0 : log1pf(__expf(v0));
                v1 = (v1 > 20.0f) ? v1 : log1pf(__expf(v1));
                v2 = (v2 > 20.0f) ? v2 : log1pf(__expf(v2));
                v3 = (v3 > 20.0f) ? v3 : log1pf(__expf(v3));
            }
            *(float2*)(C + (size_t)r0 * ldc + cc) = make_float2(v0, v1);
            *(float2*)(C + (size_t)(r0 + 8) * ldc + cc) = make_float2(v2, v3);
        }
    }
}

// ============================================================================
// fp32 -> (hi,lo) bf16 split
// ============================================================================
__global__ void split_kernel(const float* __restrict__ src,
                             __nv_bfloat16* __restrict__ hi,
                             __nv_bfloat16* __restrict__ lo, int n) {
    int i = blockIdx.x * blockDim.x + threadIdx.x;
    if (i >= n) return;
    float v = src[i];
    __nv_bfloat16 h = __float2bfloat16(v);
    hi[i] = h;
    lo[i] = __float2bfloat16(v - __bfloat162float(h));
}

// W_dt [3072,96] -> split [3072,128] zero-padded in K
__global__ void split_wdt_kernel(const float* __restrict__ src,
                                 __nv_bfloat16* __restrict__ hi,
                                 __nv_bfloat16* __restrict__ lo) {
    int idx = blockIdx.x * blockDim.x + threadIdx.x;
    if (idx >= II * 128) return;
    int k = idx & 127;
    int i = idx >> 7;
    float v = (k < RR) ? src[i * RR + k] : 0.0f;
    __nv_bfloat16 h = __float2bfloat16(v);
    hi[idx] = h;
    lo[idx] = __float2bfloat16(v - __bfloat162float(h));
}

// ============================================================================
// causal depthwise conv1d (K=4) + SiLU; writes fp32 + bf16 split
// ============================================================================
__global__ void conv_silu_kernel(const float* __restrict__ conv_w,
                                 const float* __restrict__ conv_b) {
    int idx = blockIdx.x * blockDim.x + threadIdx.x;
    if (idx >= MTOT * II) return;
    const int i = idx % II;
    const int m = idx / II;
    const int l = m & (LL - 1);

    float acc = conv_b[i];
#pragma unroll
    for (int j = 0; j < 4; j++) {
        int ls = l - 3 + j;
        if (ls >= 0) acc = fmaf(g_proj[(size_t)(m - 3 + j) * E2 + i], conv_w[i * 4 + j], acc);
    }
    float s = acc / (1.0f + __expf(-acc));
    g_x[idx] = s;
    __nv_bfloat16 h = __float2bfloat16(s);
    g_x_hi[idx] = h;
    g_x_lo[idx] = __float2bfloat16(s - __bfloat162float(h));
}

// ============================================================================
// Selective scan fused with D-skip and gate*silu(gate); writes y as bf16 split
// ============================================================================
#define SCH 32
#define NCHUNK (LL / SCH)

__global__ __launch_bounds__(128)
void scan_kernel(const float* __restrict__ Amat, const float* __restrict__ Dvec) {
    __shared__ __align__(16) float sD[2][SCH * 32];
    __shared__ __align__(16) float sX[2][SCH * 32];
    __shared__ __align__(16) float sBC[2][SCH * 32];
    __shared__ __align__(16) float sY[SCH * 32];

    const int tid = threadIdx.x;
    const int blk = blockIdx.x;
    const int b = blk / 96;
    const int ibase = (blk % 96) * 32;
    const int q = tid & 3;
    const int c = tid >> 2;
    const int i = ibase + c;
    const int mbase = b * LL;

    float a2[4];
#pragma unroll
    for (int n = 0; n < 4; n++)
        a2[n] = Amat[i * NN + q * 4 + n] * 1.4426950408889634f;
    const float dv = Dvec[i];
    float st[4] = {0.0f, 0.0f, 0.0f, 0.0f};

    auto issue = [&](int buf, int ch) {
        const int m0 = mbase + ch * SCH;
#pragma unroll
        for (int k2 = 0; k2 < 2; k2++) {
            int f = tid + k2 * 128;
            int l = f >> 3;
            int c4 = (f & 7) * 4;
            int m = m0 + l;
            cp16(&sD[buf][l * 32 + c4], &g_delta[(size_t)m * II + ibase + c4]);
            cp16(&sX[buf][l * 32 + c4], &g_x[(size_t)m * II + ibase + c4]);
            cp16(&sBC[buf][l * 32 + c4], &g_ssmp[(size_t)m * PP + RR + c4]);
        }
    };

    issue(0, 0);
    cp_commit();

    for (int ch = 0; ch < NCHUNK; ch++) {
        const int cur = ch & 1;
        if (ch + 1 < NCHUNK) {
            issue(1 - cur, ch + 1);
            cp_commit();
            cp_wait1();
        } else {
            cp_wait0();
        }
        __syncthreads();

        const int m0 = mbase + ch * SCH;
#pragma unroll 4
        for (int l = 0; l < SCH; l++) {
            const float delta = sD[cur][l * 32 + c];
            const float xv = sX[cur][l * 32 + c];
            const float du = delta * xv;
            const float4 Bv = *(const float4*)&sBC[cur][l * 32 + q * 4];
            const float4 Cv = *(const float4*)&sBC[cur][l * 32 + 16 + q * 4];
            float dA0 = fast_ex2(delta * a2[0]);
            float dA1 = fast_ex2(delta * a2[1]);
            float dA2 = fast_ex2(delta * a2[2]);
            float dA3 = fast_ex2(delta * a2[3]);
            st[0] = fmaf(st[0], dA0, du * Bv.x);
            st[1] = fmaf(st[1], dA1, du * Bv.y);
            st[2] = fmaf(st[2], dA2, du * Bv.z);
            st[3] = fmaf(st[3], dA3, du * Bv.w);
            float y = st[0] * Cv.x + st[1] * Cv.y + st[2] * Cv.z + st[3] * Cv.w;
            y += __shfl_xor_sync(0xffffffffu, y, 1);
            y += __shfl_xor_sync(0xffffffffu, y, 2);
            if (q == 0) {
                const int m = m0 + l;
                const float g = g_proj[(size_t)m * E2 + II + i];
                const float sg = g / (1.0f + __expf(-g));
                sY[l * 32 + c] = (y + xv * dv) * sg;
            }
        }
        __syncthreads();

        // store y chunk as bf16 hi/lo pairs
#pragma unroll
        for (int k2 = 0; k2 < 4; k2++) {
            int f = tid + k2 * 128;      // 0..511 pairs
            int l = f >> 4;
            int c2 = (f & 15) * 2;
            float v0 = sY[l * 32 + c2];
            float v1 = sY[l * 32 + c2 + 1];
            __nv_bfloat16 h0 = __float2bfloat16(v0);
            __nv_bfloat16 h1 = __float2bfloat16(v1);
            __nv_bfloat16 l0 = __float2bfloat16(v0 - __bfloat162float(h0));
            __nv_bfloat16 l1 = __float2bfloat16(v1 - __bfloat162float(h1));
            size_t base = ((size_t)(m0 + l) * II + ibase + c2) >> 1;
            __nv_bfloat162 ph; ph.x = h0; ph.y = h1;
            __nv_bfloat162 pl; pl.x = l0; pl.y = l1;
            ((__nv_bfloat162*)g_y_hi)[base] = ph;
            ((__nv_bfloat162*)g_y_lo)[base] = pl;
        }
    }
}

// ============================================================================
// kernel_launch
// ============================================================================
extern "C" void kernel_launch(void* const* d_in, const int* in_sizes, int n_in,
                              void* d_out, int out_size) {
    const float* hs      = (const float*)d_in[0];
    const float* W_in    = (const float*)d_in[1];
    const float* conv_w  = (const float*)d_in[2];
    const float* conv_b  = (const float*)d_in[3];
    const float* W_x     = (const float*)d_in[4];
    const float* W_dt    = (const float*)d_in[5];
    const float* dt_bias = (const float*)d_in[6];
    const float* Amat    = (const float*)d_in[7];
    const float* Dvec    = (const float*)d_in[8];
    const float* W_out   = (const float*)d_in[9];
    float* out = (float*)d_out;

    float *proj, *ssmp, *delta;
    cudaGetSymbolAddress((void**)&proj, g_proj);
    cudaGetSymbolAddress((void**)&ssmp, g_ssmp);
    cudaGetSymbolAddress((void**)&delta, g_delta);
    __nv_bfloat16 *hs_hi, *hs_lo, *Win_hi, *Win_lo, *x_hi, *x_lo, *Wx_hi, *Wx_lo;
    __nv_bfloat16 *sp_hi, *sp_lo, *Wdt_hi, *Wdt_lo, *y_hi, *y_lo, *Wout_hi, *Wout_lo;
    cudaGetSymbolAddress((void**)&hs_hi, g_hs_hi);
    cudaGetSymbolAddress((void**)&hs_lo, g_hs_lo);
    cudaGetSymbolAddress((void**)&Win_hi, g_Win_hi);
    cudaGetSymbolAddress((void**)&Win_lo, g_Win_lo);
    cudaGetSymbolAddress((void**)&x_hi, g_x_hi);
    cudaGetSymbolAddress((void**)&x_lo, g_x_lo);
    cudaGetSymbolAddress((void**)&Wx_hi, g_Wx_hi);
    cudaGetSymbolAddress((void**)&Wx_lo, g_Wx_lo);
    cudaGetSymbolAddress((void**)&sp_hi, g_sp_hi);
    cudaGetSymbolAddress((void**)&sp_lo, g_sp_lo);
    cudaGetSymbolAddress((void**)&Wdt_hi, g_Wdt_hi);
    cudaGetSymbolAddress((void**)&Wdt_lo, g_Wdt_lo);
    cudaGetSymbolAddress((void**)&y_hi, g_y_hi);
    cudaGetSymbolAddress((void**)&y_lo, g_y_lo);
    cudaGetSymbolAddress((void**)&Wout_hi, g_Wout_hi);
    cudaGetSymbolAddress((void**)&Wout_lo, g_Wout_lo);

    cudaFuncSetAttribute(gemm_mma<0>, cudaFuncAttributeMaxDynamicSharedMemorySize, GEMM_SMEM);
    cudaFuncSetAttribute(gemm_mma<1>, cudaFuncAttributeMaxDynamicSharedMemorySize, GEMM_SMEM);

    // splits of inputs/weights
    {
        int n;
        n = MTOT * HH; split_kernel<<<(n + 255) / 256, 256>>>(hs, hs_hi, hs_lo, n);
        n = E2 * HH;   split_kernel<<<(n + 255) / 256, 256>>>(W_in, Win_hi, Win_lo, n);
        n = PP * II;   split_kernel<<<(n + 255) / 256, 256>>>(W_x, Wx_hi, Wx_lo, n);
        n = HH * II;   split_kernel<<<(n + 255) / 256, 256>>>(W_out, Wout_hi, Wout_lo, n);
        n = II * 128;  split_wdt_kernel<<<(n + 255) / 256, 256>>>(W_dt, Wdt_hi, Wdt_lo);
    }

    // 1) in_proj: proj[4096,6144] = hs @ W_in^T   (K=1536)
    gemm_mma<0><<<dim3(E2 / 128, MTOT / 128), 256, GEMM_SMEM>>>(
        hs_hi, hs_lo, Win_hi, Win_lo, HH, proj, E2, nullptr);

    // 2) conv + SiLU -> g_x (+ split)
    {
        int total = MTOT * II;
        conv_silu_kernel<<<(total + 255) / 256, 256>>>(conv_w, conv_b);
    }

    // 3) x_proj: ssmp[4096,128] = x @ W_x^T   (K=3072)
    gemm_mma<0><<<dim3(1, MTOT / 128), 256, GEMM_SMEM>>>(
        x_hi, x_lo, Wx_hi, Wx_lo, II, ssmp, PP, nullptr);

    // 3b) split ssmp (full 128 cols; cols>=96 hit zero weights in dt GEMM)
    {
        int n = MTOT * PP;
        split_kernel<<<(n + 255) / 256, 256>>>(ssmp, sp_hi, sp_lo, n);
    }

    // 4) dt_proj + softplus: delta = softplus(ssmp @ W_dt^T + bias)  (K=128 padded)
    gemm_mma<1><<<dim3(II / 128, MTOT / 128), 256, GEMM_SMEM>>>(
        sp_hi, sp_lo, Wdt_hi, Wdt_lo, 128, delta, II, dt_bias);

    // 5) scan -> y split
    scan_kernel<<<192, 128>>>(Amat, Dvec);

    // 6) out_proj: out[4096,1536] = y @ W_out^T   (K=3072)
    gemm_mma<0><<<dim3(HH / 128, MTOT / 128), 256, GEMM_SMEM>>>(
        y_hi, y_lo, Wout_hi, Wout_lo, II, out, HH, nullptr);
}

// round 4
// speedup vs baseline: 4.4193x; 2.0527x over previous
#include <cuda_runtime.h>
#include <cuda_fp16.h>
#include <math.h>
#include <stdint.h>

// ---------------- problem constants ----------------
#define BB 2
#define LL 2048
#define HH 1536
#define II 3072
#define NN 16
#define RR 96
#define MTOT 4096
#define E2 6144
#define PP 128

// ---------------- fp32 scratch ----------------
__device__ __align__(256) float g_proj[(size_t)MTOT * E2];   // in_proj output [4096,6144]
__device__ __align__(256) float g_x[(size_t)MTOT * II];      // conv+silu output (scan input)
__device__ __align__(256) float g_ssmp[(size_t)MTOT * PP];   // x_proj output [4096,128]
__device__ __align__(256) float g_delta[(size_t)MTOT * II];  // softplus(dt+bias)
__device__ __align__(256) float g_part[4 * (size_t)MTOT * PP]; // x_proj split-K partials

// ---------------- fp16 scratch ----------------
__device__ __align__(256) __half g_hs16[(size_t)MTOT * HH];                        // A of in_proj
__device__ __align__(256) __half g_Win_hi[(size_t)E2 * HH],  g_Win_lo[(size_t)E2 * HH];
__device__ __align__(256) __half g_x16[(size_t)MTOT * II];                         // A of x_proj
__device__ __align__(256) __half g_Wx_hi[(size_t)PP * II],   g_Wx_lo[(size_t)PP * II];
__device__ __align__(256) __half g_sp16[(size_t)MTOT * PP];                        // A of dt_proj
__device__ __align__(256) __half g_Wdt_hi[(size_t)II * PP],  g_Wdt_lo[(size_t)II * PP]; // K pad 96->128
__device__ __align__(256) __half g_y16[(size_t)MTOT * II];                         // A of out_proj
__device__ __align__(256) __half g_Wout_hi[(size_t)HH * II], g_Wout_lo[(size_t)HH * II];

// ---------------- helpers ----------------
__device__ __forceinline__ float fast_ex2(float x) {
    float r; asm("ex2.approx.f32 %0, %1;" : "=f"(r) : "f"(x)); return r;
}
__device__ __forceinline__ uint32_t smem_u32(const void* p) {
    return (uint32_t)__cvta_generic_to_shared(p);
}
__device__ __forceinline__ void cp16(void* dst_smem, const void* src_gmem) {
    unsigned d = smem_u32(dst_smem);
    asm volatile("cp.async.cg.shared.global [%0], [%1], 16;" :: "r"(d), "l"(src_gmem));
}
__device__ __forceinline__ void cp_commit() { asm volatile("cp.async.commit_group;"); }
__device__ __forceinline__ void cp_wait2() { asm volatile("cp.async.wait_group 2;" ::: "memory"); }
__device__ __forceinline__ void cp_wait1() { asm volatile("cp.async.wait_group 1;" ::: "memory"); }
__device__ __forceinline__ void cp_wait0() { asm volatile("cp.async.wait_group 0;" ::: "memory"); }

__device__ __forceinline__ void ldsm4(uint32_t& r0, uint32_t& r1, uint32_t& r2, uint32_t& r3,
                                      uint32_t addr) {
    asm volatile("ldmatrix.sync.aligned.m8n8.x4.shared.b16 {%0,%1,%2,%3}, [%4];"
                 : "=r"(r0), "=r"(r1), "=r"(r2), "=r"(r3) : "r"(addr));
}
__device__ __forceinline__ void mma16816(float* d, const uint32_t* a, const uint32_t* b) {
    asm volatile("mma.sync.aligned.m16n8k16.row.col.f32.f16.f16.f32 "
                 "{%0,%1,%2,%3}, {%4,%5,%6,%7}, {%8,%9}, {%0,%1,%2,%3};"
                 : "+f"(d[0]), "+f"(d[1]), "+f"(d[2]), "+f"(d[3])
                 : "r"(a[0]), "r"(a[1]), "r"(a[2]), "r"(a[3]), "r"(b[0]), "r"(b[1]));
}

// ============================================================================
// fp16 2-pass GEMM via mma.sync: C[M,N] = A[M,K] * B[N,K]^T (K-contiguous)
// A single fp16; B = Bhi + Blo (weight split). C = A*Bhi + A*Blo (fp32 accum).
// 128x128 CTA tile, BK=64, 4-stage cp.async pipeline, 8 warps (2m x 4n),
// warp tile 64x32. K % 64 == 0. Split-K via blockIdx.z (partials at
// C + z*c_part_stride). EPI==1: C = softplus(C + bias[col]).
// ============================================================================
#define BK 64
#define TILE_B (128 * BK * 2)            // 16384 bytes per matrix tile
#define STAGE_B (3 * TILE_B)             // 49152 per stage (A, Bhi, Blo)
#define GEMM_SMEM (4 * STAGE_B)          // 196608

template <int EPI>
__global__ __launch_bounds__(256)
void gemm_mma(const __half* __restrict__ A,
              const __half* __restrict__ Bhi, const __half* __restrict__ Blo,
              int K, float* __restrict__ C, int ldc,
              size_t c_part_stride, const float* __restrict__ bias) {
    extern __shared__ char smem[];
    const int tid = threadIdx.x;
    const int lane = tid & 31;
    const int wid = tid >> 5;
    const int m0 = blockIdx.y * 128;
    const int n0 = blockIdx.x * 128;
    const int wm = (wid & 1) * 64;
    const int wn = (wid >> 1) * 32;
    const int ncz = (K >> 6) / gridDim.z;      // chunks this z-part
    const int c0 = blockIdx.z * ncz;           // first chunk index
    C += (size_t)blockIdx.z * c_part_stride;

    float acc[4][4][4] = {};

    auto issue = [&](int lc) {                 // lc = local chunk index
        char* st = smem + (lc & 3) * STAGE_B;
        const int k0 = (c0 + lc) << 6;
#pragma unroll
        for (int rep = 0; rep < 4; rep++) {
            int idx = tid + rep * 256;         // 0..1023
            int r = idx >> 3;                  // row 0..127
            int cc = idx & 7;                  // 16B chunk in 128B row
            uint32_t so = (uint32_t)(r * 128 + ((cc ^ (r & 7)) * 16));
            size_t ao = (size_t)(m0 + r) * K + k0 + cc * 8;
            size_t bo = (size_t)(n0 + r) * K + k0 + cc * 8;
            cp16(st + so, A + ao);
            cp16(st + TILE_B + so, Bhi + bo);
            cp16(st + 2 * TILE_B + so, Blo + bo);
        }
    };

    for (int p = 0; p < 3; p++) {
        if (p < ncz) issue(p);
        cp_commit();
    }

    const int a_row = lane & 15;
    const int a_kh = lane >> 4;
    const int b_nr = (lane & 7) + ((lane >> 4) << 3);
    const int b_kh = (lane >> 3) & 1;

    for (int lc = 0; lc < ncz; lc++) {
        cp_wait2();
        __syncthreads();
        const uint32_t sA = smem_u32(smem + (lc & 3) * STAGE_B);
        const uint32_t sBh = sA + TILE_B;
        const uint32_t sBl = sA + 2 * TILE_B;

#pragma unroll
        for (int kc = 0; kc < 8; kc += 2) {
            uint32_t af[4][4], bh[4][2], bl[4][2];
#pragma unroll
            for (int i = 0; i < 4; i++) {
                int r = wm + i * 16 + a_row;
                uint32_t off = (uint32_t)(r * 128 + (((kc + a_kh) ^ (r & 7)) * 16));
                ldsm4(af[i][0], af[i][1], af[i][2], af[i][3], sA + off);
            }
#pragma unroll
            for (int jj = 0; jj < 2; jj++) {
                int r = wn + b_nr + jj * 16;
                uint32_t off = (uint32_t)(r * 128 + (((kc + b_kh) ^ (r & 7)) * 16));
                uint32_t t0, t1, t2, t3;
                ldsm4(t0, t1, t2, t3, sBh + off);
                bh[jj * 2][0] = t0; bh[jj * 2][1] = t1;
                bh[jj * 2 + 1][0] = t2; bh[jj * 2 + 1][1] = t3;
                ldsm4(t0, t1, t2, t3, sBl + off);
                bl[jj * 2][0] = t0; bl[jj * 2][1] = t1;
                bl[jj * 2 + 1][0] = t2; bl[jj * 2 + 1][1] = t3;
            }
#pragma unroll
            for (int i = 0; i < 4; i++)
#pragma unroll
                for (int j = 0; j < 4; j++) {
                    mma16816(acc[i][j], af[i], bh[j]);
                    mma16816(acc[i][j], af[i], bl[j]);
                }
        }
        __syncthreads();
        if (lc + 3 < ncz) issue(lc + 3);
        cp_commit();
    }

    // epilogue: registers -> gmem
    const int quad = lane >> 2;
    const int tq = lane & 3;
#pragma unroll
    for (int i = 0; i < 4; i++) {
#pragma unroll
        for (int j = 0; j < 4; j++) {
            int r0 = m0 + wm + i * 16 + quad;
            int cc = n0 + wn + j * 8 + tq * 2;
            float v0 = acc[i][j][0], v1 = acc[i][j][1];
            float v2 = acc[i][j][2], v3 = acc[i][j][3];
            if (EPI == 1) {
                float b0 = bias[cc], b1 = bias[cc + 1];
                v0 += b0; v1 += b1; v2 += b0; v3 += b1;
                v0 = (v0 > 20.0f) ? v0 : log1pf(__expf(v0));
                v1 = (v1 > 20.0f) ? v1 : log1pf(__expf(v1));
                v2 = (v2 > 20.0f) ? v2 : log1pf(__expf(v2));
                v3 = (v3 > 20.0f) ? v3 : log1pf(__expf(v3));
            }
            *(float2*)(C + (size_t)r0 * ldc + cc) = make_float2(v0, v1);
            *(float2*)(C + (size_t)(r0 + 8) * ldc + cc) = make_float2(v2, v3);
        }
    }
}

// ============================================================================
// conversion kernels
// ============================================================================
__global__ void convert16_kernel(const float* __restrict__ src,
                                 __half* __restrict__ dst, int n) {
    int i = blockIdx.x * blockDim.x + threadIdx.x;
    if (i < n) dst[i] = __float2half(src[i]);
}

__global__ void split_kernel(const float* __restrict__ src,
                             __half* __restrict__ hi, __half* __restrict__ lo, int n) {
    int i = blockIdx.x * blockDim.x + threadIdx.x;
    if (i >= n) return;
    float v = src[i];
    __half h = __float2half(v);
    hi[i] = h;
    lo[i] = __float2half(v - __half2float(h));
}

// W_dt [3072,96] -> split [3072,128] zero-padded in K
__global__ void split_wdt_kernel(const float* __restrict__ src,
                                 __half* __restrict__ hi, __half* __restrict__ lo) {
    int idx = blockIdx.x * blockDim.x + threadIdx.x;
    if (idx >= II * 128) return;
    int k = idx & 127;
    int i = idx >> 7;
    float v = (k < RR) ? src[i * RR + k] : 0.0f;
    __half h = __float2half(v);
    hi[idx] = h;
    lo[idx] = __float2half(v - __half2float(h));
}

// x_proj partial reduce + fp16 convert
__global__ void reduce_ssmp_kernel() {
    int idx = blockIdx.x * blockDim.x + threadIdx.x;
    if (idx >= MTOT * PP) return;
    const size_t s = (size_t)MTOT * PP;
    float v = g_part[idx] + g_part[s + idx] + g_part[2 * s + idx] + g_part[3 * s + idx];
    g_ssmp[idx] = v;
    g_sp16[idx] = __float2half(v);
}

// ============================================================================
// causal depthwise conv1d (K=4) + SiLU; 4 timesteps per thread
// ============================================================================
__global__ void conv_silu_kernel(const float* __restrict__ conv_w,
                                 const float* __restrict__ conv_b) {
    int idx = blockIdx.x * blockDim.x + threadIdx.x;
    if (idx >= (MTOT / 4) * II) return;
    const int i = idx % II;
    const int t = idx / II;
    const int m0 = t * 4;
    const int l0 = m0 & (LL - 1);

    float w0 = conv_w[i * 4 + 0], w1 = conv_w[i * 4 + 1];
    float w2 = conv_w[i * 4 + 2], w3 = conv_w[i * 4 + 3];
    const float cb = conv_b[i];

    float v[7];
#pragma unroll
    for (int j = 0; j < 7; j++) {
        int l = l0 - 3 + j;
        v[j] = (l >= 0) ? g_proj[(size_t)(m0 - 3 + j) * E2 + i] : 0.0f;
    }
#pragma unroll
    for (int s = 0; s < 4; s++) {
        float acc = fmaf(v[s], w0, fmaf(v[s + 1], w1, fmaf(v[s + 2], w2, fmaf(v[s + 3], w3, cb))));
        float o = acc / (1.0f + __expf(-acc));
        size_t off = (size_t)(m0 + s) * II + i;
        g_x[off] = o;
        g_x16[off] = __float2half(o);
    }
}

// ============================================================================
// Selective scan + D-skip + gate*silu(gate); gate staged via cp.async too.
// Writes y as single fp16 (A of out_proj).
// ============================================================================
#define SCH 32
#define NCHUNK (LL / SCH)

__global__ __launch_bounds__(128)
void scan_kernel(const float* __restrict__ Amat, const float* __restrict__ Dvec) {
    __shared__ __align__(16) float sD[2][SCH * 32];
    __shared__ __align__(16) float sX[2][SCH * 32];
    __shared__ __align__(16) float sBC[2][SCH * 32];
    __shared__ __align__(16) float sG[2][SCH * 32];
    __shared__ __align__(16) float sY[SCH * 32];

    const int tid = threadIdx.x;
    const int blk = blockIdx.x;
    const int b = blk / 96;
    const int ibase = (blk % 96) * 32;
    const int q = tid & 3;
    const int c = tid >> 2;
    const int i = ibase + c;
    const int mbase = b * LL;

    float a2[4];
#pragma unroll
    for (int n = 0; n < 4; n++)
        a2[n] = Amat[i * NN + q * 4 + n] * 1.4426950408889634f;
    const float dv = Dvec[i];
    float st[4] = {0.0f, 0.0f, 0.0f, 0.0f};

    auto issue = [&](int buf, int ch) {
        const int m0 = mbase + ch * SCH;
#pragma unroll
        for (int k2 = 0; k2 < 2; k2++) {
            int f = tid + k2 * 128;
            int l = f >> 3;
            int c4 = (f & 7) * 4;
            int m = m0 + l;
            cp16(&sD[buf][l * 32 + c4], &g_delta[(size_t)m * II + ibase + c4]);
            cp16(&sX[buf][l * 32 + c4], &g_x[(size_t)m * II + ibase + c4]);
            cp16(&sBC[buf][l * 32 + c4], &g_ssmp[(size_t)m * PP + RR + c4]);
            cp16(&sG[buf][l * 32 + c4], &g_proj[(size_t)m * E2 + II + ibase + c4]);
        }
    };

    issue(0, 0);
    cp_commit();

    for (int ch = 0; ch < NCHUNK; ch++) {
        const int cur = ch & 1;
        if (ch + 1 < NCHUNK) {
            issue(1 - cur, ch + 1);
            cp_commit();
            cp_wait1();
        } else {
            cp_wait0();
        }
        __syncthreads();

        const int m0 = mbase + ch * SCH;
#pragma unroll 4
        for (int l = 0; l < SCH; l++) {
            const float delta = sD[cur][l * 32 + c];
            const float xv = sX[cur][l * 32 + c];
            const float du = delta * xv;
            const float4 Bv = *(const float4*)&sBC[cur][l * 32 + q * 4];
            const float4 Cv = *(const float4*)&sBC[cur][l * 32 + 16 + q * 4];
            float dA0 = fast_ex2(delta * a2[0]);
            float dA1 = fast_ex2(delta * a2[1]);
            float dA2 = fast_ex2(delta * a2[2]);
            float dA3 = fast_ex2(delta * a2[3]);
            st[0] = fmaf(st[0], dA0, du * Bv.x);
            st[1] = fmaf(st[1], dA1, du * Bv.y);
            st[2] = fmaf(st[2], dA2, du * Bv.z);
            st[3] = fmaf(st[3], dA3, du * Bv.w);
            float y = st[0] * Cv.x + st[1] * Cv.y + st[2] * Cv.z + st[3] * Cv.w;
            y += __shfl_xor_sync(0xffffffffu, y, 1);
            y += __shfl_xor_sync(0xffffffffu, y, 2);
            if (q == 0) {
                const float g = sG[cur][l * 32 + c];
                const float sg = g / (1.0f + __expf(-g));
                sY[l * 32 + c] = (y + xv * dv) * sg;
            }
        }
        __syncthreads();

        // store y chunk as fp16
#pragma unroll
        for (int k2 = 0; k2 < 4; k2++) {
            int f = tid + k2 * 128;       // 0..511 pairs
            int l = f >> 4;
            int c2 = (f & 15) * 2;
            __half2 p;
            p.x = __float2half(sY[l * 32 + c2]);
            p.y = __float2half(sY[l * 32 + c2 + 1]);
            *(__half2*)&g_y16[(size_t)(m0 + l) * II + ibase + c2] = p;
        }
    }
}

// ============================================================================
// kernel_launch
// ============================================================================
extern "C" void kernel_launch(void* const* d_in, const int* in_sizes, int n_in,
                              void* d_out, int out_size) {
    const float* hs      = (const float*)d_in[0];
    const float* W_in    = (const float*)d_in[1];
    const float* conv_w  = (const float*)d_in[2];
    const float* conv_b  = (const float*)d_in[3];
    const float* W_x     = (const float*)d_in[4];
    const float* W_dt    = (const float*)d_in[5];
    const float* dt_bias = (const float*)d_in[6];
    const float* Amat    = (const float*)d_in[7];
    const float* Dvec    = (const float*)d_in[8];
    const float* W_out   = (const float*)d_in[9];
    float* out = (float*)d_out;

    float *proj, *delta, *part;
    cudaGetSymbolAddress((void**)&proj, g_proj);
    cudaGetSymbolAddress((void**)&delta, g_delta);
    cudaGetSymbolAddress((void**)&part, g_part);
    __half *hs16, *Win_hi, *Win_lo, *x16, *Wx_hi, *Wx_lo;
    __half *sp16, *Wdt_hi, *Wdt_lo, *y16, *Wout_hi, *Wout_lo;
    cudaGetSymbolAddress((void**)&hs16, g_hs16);
    cudaGetSymbolAddress((void**)&Win_hi, g_Win_hi);
    cudaGetSymbolAddress((void**)&Win_lo, g_Win_lo);
    cudaGetSymbolAddress((void**)&x16, g_x16);
    cudaGetSymbolAddress((void**)&Wx_hi, g_Wx_hi);
    cudaGetSymbolAddress((void**)&Wx_lo, g_Wx_lo);
    cudaGetSymbolAddress((void**)&sp16, g_sp16);
    cudaGetSymbolAddress((void**)&Wdt_hi, g_Wdt_hi);
    cudaGetSymbolAddress((void**)&Wdt_lo, g_Wdt_lo);
    cudaGetSymbolAddress((void**)&y16, g_y16);
    cudaGetSymbolAddress((void**)&Wout_hi, g_Wout_hi);
    cudaGetSymbolAddress((void**)&Wout_lo, g_Wout_lo);

    cudaFuncSetAttribute(gemm_mma<0>, cudaFuncAttributeMaxDynamicSharedMemorySize, GEMM_SMEM);
    cudaFuncSetAttribute(gemm_mma<1>, cudaFuncAttributeMaxDynamicSharedMemorySize, GEMM_SMEM);

    // conversions
    {
        int n;
        n = MTOT * HH; convert16_kernel<<<(n + 255) / 256, 256>>>(hs, hs16, n);
        n = E2 * HH;   split_kernel<<<(n + 255) / 256, 256>>>(W_in, Win_hi, Win_lo, n);
        n = PP * II;   split_kernel<<<(n + 255) / 256, 256>>>(W_x, Wx_hi, Wx_lo, n);
        n = HH * II;   split_kernel<<<(n + 255) / 256, 256>>>(W_out, Wout_hi, Wout_lo, n);
        n = II * 128;  split_wdt_kernel<<<(n + 255) / 256, 256>>>(W_dt, Wdt_hi, Wdt_lo);
    }

    // 1) in_proj: proj[4096,6144] = hs @ W_in^T  (K=1536)
    gemm_mma<0><<<dim3(E2 / 128, MTOT / 128, 1), 256, GEMM_SMEM>>>(
        hs16, Win_hi, Win_lo, HH, proj, E2, 0, nullptr);

    // 2) conv + SiLU -> g_x fp32 + g_x16 fp16
    {
        int total = (MTOT / 4) * II;
        conv_silu_kernel<<<(total + 255) / 256, 256>>>(conv_w, conv_b);
    }

    // 3) x_proj split-K(4): partials = x @ W_x^T  (K=3072)
    gemm_mma<0><<<dim3(1, MTOT / 128, 4), 256, GEMM_SMEM>>>(
        x16, Wx_hi, Wx_lo, II, part, PP, (size_t)MTOT * PP, nullptr);
    {
        int n = MTOT * PP;
        reduce_ssmp_kernel<<<(n + 255) / 256, 256>>>();
    }

    // 4) dt_proj + softplus: delta = softplus(ssmp @ W_dt^T + bias)  (K=128 padded)
    gemm_mma<1><<<dim3(II / 128, MTOT / 128, 1), 256, GEMM_SMEM>>>(
        sp16, Wdt_hi, Wdt_lo, 128, delta, II, 0, dt_bias);

    // 5) scan -> y fp16
    scan_kernel<<<192, 128>>>(Amat, Dvec);

    // 6) out_proj: out[4096,1536] = y @ W_out^T  (K=3072)
    gemm_mma<0><<<dim3(HH / 128, MTOT / 128, 1), 256, GEMM_SMEM>>>(
        y16, Wout_hi, Wout_lo, II, out, HH, 0, nullptr);
}